// round 5
// baseline (speedup 1.0000x reference)
#include <cuda_runtime.h>
#include <math.h>
#include <float.h>

// ICP, fully persistent: ONE kernel does prep + 20 gated iterations
// (brute-force 1-NN with f32x2 FMA + FMNMX inner loop, chunk-rescan argmin,
// fused last-block Kabsch) + final best-fit. Software grid barriers with
// per-slot counters; all 256 blocks are single-wave resident on GB300.

#define NPTS 8192
#define NQ   (NPTS / 4)
#define MAX_ITERS 20
#define NB   256                 // blocks (single wave: 2/SM x 148 SMs >= 256)
#define TPB  256                 // 65536 threads, 8 partitions per src point
#define CHUNKS 16
#define CSTEPS 16                // 16*16 quads = 1024 pts per thread
#define NBAR (MAX_ITERS + 2)     // slot 0 = init, 1..20 = iters, 21 = fred

typedef unsigned long long ull;

struct BQ { ulonglong2 x, y, z, w; };   // 64B: packed quad SoA

__device__ float4 g_src4[NPTS];
__device__ float4 g_B4[NPTS];
__device__ BQ     g_Bq[NQ];
__device__ double g_part[NB][16];
__device__ float  g_T[12];
__device__ int    g_done, g_apply;
__device__ float  g_prev_err;
__device__ int    g_bar[NBAR];

__device__ __forceinline__ ull pk2(float lo, float hi) {
    ull r; asm("mov.b64 %0,{%1,%2};" : "=l"(r) : "f"(lo), "f"(hi)); return r;
}
__device__ __forceinline__ ull fma2(ull a, ull b, ull c) {
    ull d; asm("fma.rn.f32x2 %0,%1,%2,%3;" : "=l"(d) : "l"(a), "l"(b), "l"(c)); return d;
}
__device__ __forceinline__ void upk2(ull v, float& lo, float& hi) {
    asm("mov.b64 {%0,%1},%2;" : "=f"(lo), "=f"(hi) : "l"(v));
}

// ---------------------------------------------------------------------------
__device__ void kabsch3(const float H[9], const float cA[3], const float cB[3],
                        float R[9], float t[3]) {
    float K[3][3], V[3][3];
    #pragma unroll
    for (int i = 0; i < 3; ++i)
        #pragma unroll
        for (int j = 0; j < 3; ++j) {
            K[i][j] = H[0+i]*H[0+j] + H[3+i]*H[3+j] + H[6+i]*H[6+j];
            V[i][j] = (i == j) ? 1.0f : 0.0f;
        }
    const int pq[3][2] = {{0,1},{0,2},{1,2}};
    for (int sw = 0; sw < 8; ++sw) {
        for (int r3 = 0; r3 < 3; ++r3) {
            int p = pq[r3][0], q = pq[r3][1];
            float apq = K[p][q];
            if (fabsf(apq) < 1e-25f) continue;
            float theta = (K[q][q] - K[p][p]) / (2.0f * apq);
            float tt = 1.0f / (fabsf(theta) + sqrtf(theta*theta + 1.0f));
            if (theta < 0.0f) tt = -tt;
            float c = rsqrtf(tt*tt + 1.0f);
            float s = tt * c;
            #pragma unroll
            for (int r = 0; r < 3; ++r) {
                float kp = K[r][p], kq = K[r][q];
                K[r][p] = c*kp - s*kq; K[r][q] = s*kp + c*kq;
            }
            #pragma unroll
            for (int cc = 0; cc < 3; ++cc) {
                float kp = K[p][cc], kq = K[q][cc];
                K[p][cc] = c*kp - s*kq; K[q][cc] = s*kp + c*kq;
            }
            #pragma unroll
            for (int r = 0; r < 3; ++r) {
                float vp = V[r][p], vq = V[r][q];
                V[r][p] = c*vp - s*vq; V[r][q] = s*vp + c*vq;
            }
        }
    }
    float lam[3] = {K[0][0], K[1][1], K[2][2]};
    int ord[3] = {0, 1, 2};
    #pragma unroll
    for (int a = 0; a < 2; ++a)
        #pragma unroll
        for (int b = 0; b < 2 - a; ++b)
            if (lam[ord[b]] < lam[ord[b+1]]) { int tmp = ord[b]; ord[b] = ord[b+1]; ord[b+1] = tmp; }
    float Vs[3][3];
    #pragma unroll
    for (int k = 0; k < 3; ++k)
        #pragma unroll
        for (int r = 0; r < 3; ++r) Vs[r][k] = V[r][ord[k]];

    float U[3][3], sig[3];
    #pragma unroll
    for (int k = 0; k < 3; ++k) {
        float u0 = H[0]*Vs[0][k] + H[1]*Vs[1][k] + H[2]*Vs[2][k];
        float u1 = H[3]*Vs[0][k] + H[4]*Vs[1][k] + H[5]*Vs[2][k];
        float u2 = H[6]*Vs[0][k] + H[7]*Vs[1][k] + H[8]*Vs[2][k];
        float n = sqrtf(u0*u0 + u1*u1 + u2*u2);
        sig[k] = n;
        float inv = (n > 1e-25f) ? 1.0f / n : 0.0f;
        U[0][k] = u0*inv; U[1][k] = u1*inv; U[2][k] = u2*inv;
    }
    if (sig[2] <= 1e-10f * sig[0]) {
        float u0 = U[1][0]*U[2][1] - U[2][0]*U[1][1];
        float u1 = U[2][0]*U[0][1] - U[0][0]*U[2][1];
        float u2 = U[0][0]*U[1][1] - U[1][0]*U[0][1];
        float n = rsqrtf(fmaxf(u0*u0 + u1*u1 + u2*u2, 1e-30f));
        U[0][2] = u0*n; U[1][2] = u1*n; U[2][2] = u2*n;
    }
    float R0[3][3];
    #pragma unroll
    for (int i = 0; i < 3; ++i)
        #pragma unroll
        for (int j = 0; j < 3; ++j)
            R0[i][j] = Vs[i][0]*U[j][0] + Vs[i][1]*U[j][1] + Vs[i][2]*U[j][2];
    float det = R0[0][0]*(R0[1][1]*R0[2][2] - R0[1][2]*R0[2][1])
              - R0[0][1]*(R0[1][0]*R0[2][2] - R0[1][2]*R0[2][0])
              + R0[0][2]*(R0[1][0]*R0[2][1] - R0[1][1]*R0[2][0]);
    if (det < 0.0f) {
        #pragma unroll
        for (int i = 0; i < 3; ++i) Vs[i][2] = -Vs[i][2];
        #pragma unroll
        for (int i = 0; i < 3; ++i)
            #pragma unroll
            for (int j = 0; j < 3; ++j)
                R0[i][j] = Vs[i][0]*U[j][0] + Vs[i][1]*U[j][1] + Vs[i][2]*U[j][2];
    }
    #pragma unroll
    for (int i = 0; i < 3; ++i) {
        #pragma unroll
        for (int j = 0; j < 3; ++j) R[i*3+j] = R0[i][j];
        t[i] = cB[i] - (R0[i][0]*cA[0] + R0[i][1]*cA[1] + R0[i][2]*cA[2]);
    }
}

__device__ void solve_iter(const double S[16]) {
    const double N = (double)NPTS;
    double cAd[3] = {S[0]/N, S[1]/N, S[2]/N};
    double cBd[3] = {S[3]/N, S[4]/N, S[5]/N};
    float H[9], cA[3], cB[3];
    #pragma unroll
    for (int r = 0; r < 3; ++r) {
        cA[r] = (float)cAd[r]; cB[r] = (float)cBd[r];
        #pragma unroll
        for (int c = 0; c < 3; ++c)
            H[r*3+c] = (float)(S[6 + 3*r + c]/N - cAd[r]*cBd[c]);
    }
    float R[9], t[3];
    kabsch3(H, cA, cB, R, t);
    #pragma unroll
    for (int q = 0; q < 9; ++q) g_T[q] = R[q];
    g_T[9] = t[0]; g_T[10] = t[1]; g_T[11] = t[2];
    float errf = (float)(S[15] / N);
    int conv = fabsf(g_prev_err - errf) < 1e-3f;
    g_prev_err = errf;
    g_apply = 1;
    if (conv) g_done = 1;
}

// block-level reduce of v[16] into g_part[bid]; writers fence before return.
__device__ __forceinline__ void block_reduce16(double v[16], double sm[8][16],
                                               int tid, int bid) {
    #pragma unroll
    for (int q = 0; q < 16; ++q) {
        #pragma unroll
        for (int off = 16; off > 0; off >>= 1)
            v[q] += __shfl_down_sync(0xffffffffu, v[q], off);
    }
    int warp = tid >> 5, lane = tid & 31;
    if (lane == 0) {
        #pragma unroll
        for (int q = 0; q < 16; ++q) sm[warp][q] = v[q];
    }
    __syncthreads();
    if (tid < 16) {
        double acc = 0.0;
        #pragma unroll
        for (int w = 0; w < 8; ++w) acc += sm[w][tid];
        g_part[bid][tid] = acc;
        __threadfence();
    }
    __syncthreads();
}

// last-block reduce of all NB partial rows -> S[16]; returns true on tid 0.
__device__ __forceinline__ void grid_sum16(double S[16], double sm[8][16], int tid) {
    double w[16];
    #pragma unroll
    for (int q = 0; q < 16; ++q) w[q] = g_part[tid][q];
    #pragma unroll
    for (int q = 0; q < 16; ++q) {
        #pragma unroll
        for (int off = 16; off > 0; off >>= 1)
            w[q] += __shfl_down_sync(0xffffffffu, w[q], off);
    }
    int warp = tid >> 5, lane = tid & 31;
    __syncthreads();
    if (lane == 0) {
        #pragma unroll
        for (int q = 0; q < 16; ++q) sm[warp][q] = w[q];
    }
    __syncthreads();
    if (tid == 0) {
        #pragma unroll
        for (int q = 0; q < 16; ++q)
            S[q] = sm[0][q] + sm[1][q] + sm[2][q] + sm[3][q]
                 + sm[4][q] + sm[5][q] + sm[6][q] + sm[7][q];
    }
}

// ---------------------------------------------------------------------------
__global__ void __launch_bounds__(TPB) k_icp(const float* __restrict__ A,
                                             const float* __restrict__ B,
                                             float* __restrict__ out) {
    __shared__ double sm[8][16];
    __shared__ int slast;
    const int tid = threadIdx.x;
    const int bid = blockIdx.x;
    const int gt  = bid * TPB + tid;
    const int i   = gt >> 3;           // src point
    const int part = gt & 7;           // partition

    // ---- init phase ----
    if (gt < NPTS) {
        float ax = A[3*gt], ay = A[3*gt+1], az = A[3*gt+2];
        g_src4[gt] = make_float4(ax, ay, az, ax*ax + ay*ay + az*az);
        float bx = B[3*gt], by = B[3*gt+1], bz = B[3*gt+2];
        g_B4[gt]   = make_float4(bx, by, bz, bx*bx + by*by + bz*bz);
    }
    if (gt < NQ) {
        const float4* B4 = (const float4*)B;
        float4 f0 = B4[3*gt], f1 = B4[3*gt+1], f2 = B4[3*gt+2];
        float x0=f0.x, y0=f0.y, z0=f0.z;
        float x1=f0.w, y1=f1.x, z1=f1.y;
        float x2=f1.z, y2=f1.w, z2=f2.x;
        float x3=f2.y, y3=f2.z, z3=f2.w;
        *(float4*)&g_Bq[gt].x = make_float4(x0, x1, x2, x3);
        *(float4*)&g_Bq[gt].y = make_float4(y0, y1, y2, y3);
        *(float4*)&g_Bq[gt].z = make_float4(z0, z1, z2, z3);
        *(float4*)&g_Bq[gt].w = make_float4(x0*x0+y0*y0+z0*z0, x1*x1+y1*y1+z1*z1,
                                            x2*x2+y2*y2+z2*z2, x3*x3+y3*y3+z3*z3);
    }
    if (gt == 0) { g_done = 0; g_apply = 0; g_prev_err = 0.f; }

    // init barrier (slot 0): plain arrive + spin (last arriver releases all)
    __syncthreads();
    __threadfence();
    if (tid == 0) {
        atomicAdd(&g_bar[0], 1);
        while (atomicAdd(&g_bar[0], 0) < NB) __nanosleep(32);
        __threadfence();
    }
    __syncthreads();

    // ---- iteration loop ----
    for (int it = 0; it < MAX_ITERS; ++it) {
        if (*(volatile int*)&g_done) break;

        float4 s = g_src4[i];
        float sx = s.x, sy = s.y, sz = s.z;
        if (*(volatile int*)&g_apply) {
            float x = g_T[0]*sx + g_T[1]*sy + g_T[2]*sz + g_T[9];
            float y = g_T[3]*sx + g_T[4]*sy + g_T[5]*sz + g_T[10];
            float z = g_T[6]*sx + g_T[7]*sy + g_T[8]*sz + g_T[11];
            sx = x; sy = y; sz = z;
            if (part == 0) g_src4[i] = make_float4(sx, sy, sz, sx*sx + sy*sy + sz*sz);
        }

        ull mx2 = pk2(-2.f*sx, -2.f*sx);
        ull my2 = pk2(-2.f*sy, -2.f*sy);
        ull mz2 = pk2(-2.f*sz, -2.f*sz);

        float b0 = FLT_MAX, b1 = FLT_MAX, b2 = FLT_MAX, b3 = FLT_MAX;
        float gbest = FLT_MAX;
        int   cbest = 0;
        int   q = part;
        for (int c = 0; c < CHUNKS; ++c) {
            #pragma unroll 4
            for (int kk = 0; kk < CSTEPS; ++kk) {
                ulonglong2 xv = g_Bq[q].x, yv = g_Bq[q].y;
                ulonglong2 zv = g_Bq[q].z, wv = g_Bq[q].w;
                ull t01 = fma2(zv.x, mz2, wv.x);
                t01 = fma2(yv.x, my2, t01);
                t01 = fma2(xv.x, mx2, t01);
                ull t23 = fma2(zv.y, mz2, wv.y);
                t23 = fma2(yv.y, my2, t23);
                t23 = fma2(xv.y, mx2, t23);
                float f0, f1, f2, f3;
                upk2(t01, f0, f1); upk2(t23, f2, f3);
                b0 = fminf(b0, f0); b1 = fminf(b1, f1);
                b2 = fminf(b2, f2); b3 = fminf(b3, f3);
                q += 8;
            }
            float m = fminf(fminf(b0, b1), fminf(b2, b3));
            if (m < gbest) { gbest = m; cbest = c; }
        }

        // rescan the last-improving chunk for argmin index (bit-exact)
        int bj = NPTS - 1;
        {
            int qq = part + 8 * (cbest * CSTEPS);
            for (int kk = 0; kk < CSTEPS; ++kk) {
                ulonglong2 xv = g_Bq[qq].x, yv = g_Bq[qq].y;
                ulonglong2 zv = g_Bq[qq].z, wv = g_Bq[qq].w;
                ull t01 = fma2(zv.x, mz2, wv.x);
                t01 = fma2(yv.x, my2, t01);
                t01 = fma2(xv.x, mx2, t01);
                ull t23 = fma2(zv.y, mz2, wv.y);
                t23 = fma2(yv.y, my2, t23);
                t23 = fma2(xv.y, mx2, t23);
                float f0, f1, f2, f3;
                upk2(t01, f0, f1); upk2(t23, f2, f3);
                int j0 = 4 * qq;
                if (f3 == gbest) bj = min(bj, j0 + 3);
                if (f2 == gbest) bj = min(bj, j0 + 2);
                if (f1 == gbest) bj = min(bj, j0 + 1);
                if (f0 == gbest) bj = min(bj, j0 + 0);
                qq += 8;
            }
        }

        float best = gbest;
        #pragma unroll
        for (int off = 1; off < 8; off <<= 1) {
            float od = __shfl_xor_sync(0xffffffffu, best, off);
            int   oj = __shfl_xor_sync(0xffffffffu, bj,   off);
            if (od < best || (od == best && oj < bj)) { best = od; bj = oj; }
        }

        float4 b = g_B4[bj];
        float ss = sx*sx + sy*sy + sz*sz;
        double v[16];
        {
            double dsx = sx, dsy = sy, dsz = sz;
            double dbx = b.x, dby = b.y, dbz = b.z;
            v[0] = dsx;  v[1] = dsy;  v[2] = dsz;
            v[3] = dbx;  v[4] = dby;  v[5] = dbz;
            v[6]  = dsx*dbx; v[7]  = dsx*dby; v[8]  = dsx*dbz;
            v[9]  = dsy*dbx; v[10] = dsy*dby; v[11] = dsy*dbz;
            v[12] = dsz*dbx; v[13] = dsz*dby; v[14] = dsz*dbz;
            v[15] = (double)sqrtf(fmaxf(best + ss, 0.0f) + 1e-12f);
        }
        // groups replicated over 8 lanes: scale-correct via one-lane mask trick:
        // sum 4 distinct points per warp (lanes 0,8,16,24 hold distinct points)
        #pragma unroll
        for (int qi = 0; qi < 16; ++qi) {
            v[qi] += __shfl_xor_sync(0xffffffffu, v[qi], 8);
            v[qi] += __shfl_xor_sync(0xffffffffu, v[qi], 16);
        }
        // each lane now holds 4x replication of 4-point sum; warp-reduce in
        // block_reduce16 would overcount -> divide by 8 replication first
        // (matches R3: there v was per-thread distinct only on lane0 of each
        //  8-group; here replicate-safe path: zero all but part==0 lanes)
        if (part != 0) {
            #pragma unroll
            for (int qi = 0; qi < 16; ++qi) v[qi] = 0.0;
        } else {
            // v currently = sum over the warp's 4 points (replicated);
            // keep only lane 0 & 8 &16&24? part==0 lanes are 0,8,16,24 and each
            // holds the same 4-point sum -> keep just lane 0's copy
            if ((tid & 31) != 0) {
                #pragma unroll
                for (int qi = 0; qi < 16; ++qi) v[qi] = 0.0;
            }
        }
        block_reduce16(v, sm, tid, bid);

        // iteration barrier with embedded solve (slot 1+it)
        int slot = 1 + it;
        if (tid == 0) slast = (atomicAdd(&g_bar[slot], 1) == NB - 1);
        __syncthreads();
        if (slast) {
            if (tid == 0) __threadfence();   // flush L1: fresh g_part
            __syncthreads();
            double S[16];
            grid_sum16(S, sm, tid);
            if (tid == 0) {
                solve_iter(S);
                __threadfence();
                atomicAdd(&g_bar[slot], 1);  // release -> NB+1
            }
            __syncthreads();
        } else {
            if (tid == 0) {
                while (atomicAdd(&g_bar[slot], 0) <= NB) __nanosleep(32);
                __threadfence();             // flush L1: fresh g_T/g_done
            }
            __syncthreads();
        }
    }

    // ---- final best-fit A -> src ----
    double v[16];
    if (bid < NPTS / TPB) {
        int i2 = bid * TPB + tid;
        float4 s = g_src4[i2];
        float sx = s.x, sy = s.y, sz = s.z;
        if (*(volatile int*)&g_apply) {
            float x = g_T[0]*sx + g_T[1]*sy + g_T[2]*sz + g_T[9];
            float y = g_T[3]*sx + g_T[4]*sy + g_T[5]*sz + g_T[10];
            float z = g_T[6]*sx + g_T[7]*sy + g_T[8]*sz + g_T[11];
            sx = x; sy = y; sz = z;
        }
        float ax = A[3*i2], ay = A[3*i2+1], az = A[3*i2+2];
        double pax = ax, pay = ay, paz = az;
        double pbx = sx, pby = sy, pbz = sz;
        v[0] = pax; v[1] = pay; v[2] = paz;
        v[3] = pbx; v[4] = pby; v[5] = pbz;
        v[6]  = pax*pbx; v[7]  = pax*pby; v[8]  = pax*pbz;
        v[9]  = pay*pbx; v[10] = pay*pby; v[11] = pay*pbz;
        v[12] = paz*pbx; v[13] = paz*pby; v[14] = paz*pbz;
        v[15] = 0.0;
    } else {
        #pragma unroll
        for (int qi = 0; qi < 16; ++qi) v[qi] = 0.0;
    }
    block_reduce16(v, sm, tid, bid);

    if (tid == 0) slast = (atomicAdd(&g_bar[NBAR - 1], 1) == NB - 1);
    __syncthreads();
    if (!slast) return;                      // non-final blocks exit

    if (tid == 0) __threadfence();           // flush L1: fresh g_part
    __syncthreads();
    double S[16];
    grid_sum16(S, sm, tid);
    if (tid == 0) {
        const double N = (double)NPTS;
        double cAd[3] = {S[0]/N, S[1]/N, S[2]/N};
        double cBd[3] = {S[3]/N, S[4]/N, S[5]/N};
        float H[9], cA[3], cB[3];
        #pragma unroll
        for (int r = 0; r < 3; ++r) {
            cA[r] = (float)cAd[r]; cB[r] = (float)cBd[r];
            #pragma unroll
            for (int c = 0; c < 3; ++c)
                H[r*3+c] = (float)(S[6 + 3*r + c]/N - cAd[r]*cBd[c]);
        }
        float R[9], t[3];
        kabsch3(H, cA, cB, R, t);
        #pragma unroll
        for (int r = 0; r < 3; ++r) {
            out[r*4+0] = R[r*3+0]; out[r*4+1] = R[r*3+1];
            out[r*4+2] = R[r*3+2]; out[r*4+3] = t[r];
        }
        out[12] = 0.f; out[13] = 0.f; out[14] = 0.f; out[15] = 1.f;
        #pragma unroll
        for (int sl = 0; sl < NBAR; ++sl) g_bar[sl] = 0;   // rearm for replay
    }
}

// ---------------------------------------------------------------------------
extern "C" void kernel_launch(void* const* d_in, const int* in_sizes, int n_in,
                              void* d_out, int out_size) {
    const float* A = (const float*)d_in[0];
    const float* B = (const float*)d_in[1];
    float* out = (float*)d_out;
    k_icp<<<NB, TPB>>>(A, B, out);
}

// round 8
// speedup vs baseline: 1.7903x; 1.7903x over previous
#include <cuda_runtime.h>
#include <math.h>
#include <float.h>

// ICP, fully persistent single kernel:
//   build uniform grid over B (count/scan/scatter, in-kernel) ->
//   20 gated iterations of (lazy-apply + warp-per-query grid 1-NN + Kabsch) ->
//   final best-fit.  Software grid barriers, device-side convergence latch.

#define NPTS 8192
#define MAX_ITERS 20
#define NB   256
#define TPB  256                  // 2048 warps; 4 queries per warp
#define G    48
#define G3   (G*G*G)              // 110592
#define CPAD 131072               // padded cells (2 per thread)
#define GLO  (-6.0f)
#define GH   (0.25f)
#define GINVH (4.0f)
#define NBAR 26                   // 0..4 build, 5..24 iters, 25 final

__device__ float4 g_src4[NPTS];
__device__ float4 g_B4[NPTS];
__device__ float4 g_cellPts[NPTS];        // grid-sorted B, w = index bits
__device__ int    g_cellCnt[CPAD];        // counts, then scatter cursors
__device__ int    g_cellStart[CPAD + 1];
__device__ int    g_bsum[NB];
__device__ double g_part[NB][16];
__device__ float  g_T[12];
__device__ int    g_done, g_apply;
__device__ float  g_prev_err;
__device__ int    g_bar[NBAR];

// ---------------------------------------------------------------------------
__device__ void kabsch3(const float H[9], const float cA[3], const float cB[3],
                        float R[9], float t[3]) {
    float K[3][3], V[3][3];
    #pragma unroll
    for (int i = 0; i < 3; ++i)
        #pragma unroll
        for (int j = 0; j < 3; ++j) {
            K[i][j] = H[0+i]*H[0+j] + H[3+i]*H[3+j] + H[6+i]*H[6+j];
            V[i][j] = (i == j) ? 1.0f : 0.0f;
        }
    const int pq[3][2] = {{0,1},{0,2},{1,2}};
    for (int sw = 0; sw < 8; ++sw) {
        for (int r3 = 0; r3 < 3; ++r3) {
            int p = pq[r3][0], q = pq[r3][1];
            float apq = K[p][q];
            if (fabsf(apq) < 1e-25f) continue;
            float theta = (K[q][q] - K[p][p]) / (2.0f * apq);
            float tt = 1.0f / (fabsf(theta) + sqrtf(theta*theta + 1.0f));
            if (theta < 0.0f) tt = -tt;
            float c = rsqrtf(tt*tt + 1.0f);
            float s = tt * c;
            #pragma unroll
            for (int r = 0; r < 3; ++r) {
                float kp = K[r][p], kq = K[r][q];
                K[r][p] = c*kp - s*kq; K[r][q] = s*kp + c*kq;
            }
            #pragma unroll
            for (int cc = 0; cc < 3; ++cc) {
                float kp = K[p][cc], kq = K[q][cc];
                K[p][cc] = c*kp - s*kq; K[q][cc] = s*kp + c*kq;
            }
            #pragma unroll
            for (int r = 0; r < 3; ++r) {
                float vp = V[r][p], vq = V[r][q];
                V[r][p] = c*vp - s*vq; V[r][q] = s*vp + c*vq;
            }
        }
    }
    float lam[3] = {K[0][0], K[1][1], K[2][2]};
    int ord[3] = {0, 1, 2};
    #pragma unroll
    for (int a = 0; a < 2; ++a)
        #pragma unroll
        for (int b = 0; b < 2 - a; ++b)
            if (lam[ord[b]] < lam[ord[b+1]]) { int tmp = ord[b]; ord[b] = ord[b+1]; ord[b+1] = tmp; }
    float Vs[3][3];
    #pragma unroll
    for (int k = 0; k < 3; ++k)
        #pragma unroll
        for (int r = 0; r < 3; ++r) Vs[r][k] = V[r][ord[k]];

    float U[3][3], sig[3];
    #pragma unroll
    for (int k = 0; k < 3; ++k) {
        float u0 = H[0]*Vs[0][k] + H[1]*Vs[1][k] + H[2]*Vs[2][k];
        float u1 = H[3]*Vs[0][k] + H[4]*Vs[1][k] + H[5]*Vs[2][k];
        float u2 = H[6]*Vs[0][k] + H[7]*Vs[1][k] + H[8]*Vs[2][k];
        float n = sqrtf(u0*u0 + u1*u1 + u2*u2);
        sig[k] = n;
        float inv = (n > 1e-25f) ? 1.0f / n : 0.0f;
        U[0][k] = u0*inv; U[1][k] = u1*inv; U[2][k] = u2*inv;
    }
    if (sig[2] <= 1e-10f * sig[0]) {
        float u0 = U[1][0]*U[2][1] - U[2][0]*U[1][1];
        float u1 = U[2][0]*U[0][1] - U[0][0]*U[2][1];
        float u2 = U[0][0]*U[1][1] - U[1][0]*U[0][1];
        float n = rsqrtf(fmaxf(u0*u0 + u1*u1 + u2*u2, 1e-30f));
        U[0][2] = u0*n; U[1][2] = u1*n; U[2][2] = u2*n;
    }
    float R0[3][3];
    #pragma unroll
    for (int i = 0; i < 3; ++i)
        #pragma unroll
        for (int j = 0; j < 3; ++j)
            R0[i][j] = Vs[i][0]*U[j][0] + Vs[i][1]*U[j][1] + Vs[i][2]*U[j][2];
    float det = R0[0][0]*(R0[1][1]*R0[2][2] - R0[1][2]*R0[2][1])
              - R0[0][1]*(R0[1][0]*R0[2][2] - R0[1][2]*R0[2][0])
              + R0[0][2]*(R0[1][0]*R0[2][1] - R0[1][1]*R0[2][0]);
    if (det < 0.0f) {
        #pragma unroll
        for (int i = 0; i < 3; ++i) Vs[i][2] = -Vs[i][2];
        #pragma unroll
        for (int i = 0; i < 3; ++i)
            #pragma unroll
            for (int j = 0; j < 3; ++j)
                R0[i][j] = Vs[i][0]*U[j][0] + Vs[i][1]*U[j][1] + Vs[i][2]*U[j][2];
    }
    #pragma unroll
    for (int i = 0; i < 3; ++i) {
        #pragma unroll
        for (int j = 0; j < 3; ++j) R[i*3+j] = R0[i][j];
        t[i] = cB[i] - (R0[i][0]*cA[0] + R0[i][1]*cA[1] + R0[i][2]*cA[2]);
    }
}

__device__ void solve_iter(const double S[16]) {
    const double N = (double)NPTS;
    double cAd[3] = {S[0]/N, S[1]/N, S[2]/N};
    double cBd[3] = {S[3]/N, S[4]/N, S[5]/N};
    float H[9], cA[3], cB[3];
    #pragma unroll
    for (int r = 0; r < 3; ++r) {
        cA[r] = (float)cAd[r]; cB[r] = (float)cBd[r];
        #pragma unroll
        for (int c = 0; c < 3; ++c)
            H[r*3+c] = (float)(S[6 + 3*r + c]/N - cAd[r]*cBd[c]);
    }
    float R[9], t[3];
    kabsch3(H, cA, cB, R, t);
    #pragma unroll
    for (int q = 0; q < 9; ++q) g_T[q] = R[q];
    g_T[9] = t[0]; g_T[10] = t[1]; g_T[11] = t[2];
    float errf = (float)(S[15] / N);
    int conv = fabsf(g_prev_err - errf) < 1e-3f;
    g_prev_err = errf;
    g_apply = 1;
    if (conv) g_done = 1;
}

// ---------------------------------------------------------------------------
__device__ __forceinline__ void block_reduce16(double v[16], double sm[8][16],
                                               int tid, int bid) {
    #pragma unroll
    for (int q = 0; q < 16; ++q) {
        #pragma unroll
        for (int off = 16; off > 0; off >>= 1)
            v[q] += __shfl_down_sync(0xffffffffu, v[q], off);
    }
    int warp = tid >> 5, lane = tid & 31;
    if (lane == 0) {
        #pragma unroll
        for (int q = 0; q < 16; ++q) sm[warp][q] = v[q];
    }
    __syncthreads();
    if (tid < 16) {
        double acc = 0.0;
        #pragma unroll
        for (int w = 0; w < 8; ++w) acc += sm[w][tid];
        g_part[bid][tid] = acc;
        __threadfence();
    }
    __syncthreads();
}

__device__ __forceinline__ void grid_sum16(double S[16], double sm[8][16], int tid) {
    double w[16];
    #pragma unroll
    for (int q = 0; q < 16; ++q) w[q] = g_part[tid][q];
    #pragma unroll
    for (int q = 0; q < 16; ++q) {
        #pragma unroll
        for (int off = 16; off > 0; off >>= 1)
            w[q] += __shfl_down_sync(0xffffffffu, w[q], off);
    }
    int warp = tid >> 5, lane = tid & 31;
    __syncthreads();
    if (lane == 0) {
        #pragma unroll
        for (int q = 0; q < 16; ++q) sm[warp][q] = w[q];
    }
    __syncthreads();
    if (tid == 0) {
        #pragma unroll
        for (int q = 0; q < 16; ++q)
            S[q] = sm[0][q] + sm[1][q] + sm[2][q] + sm[3][q]
                 + sm[4][q] + sm[5][q] + sm[6][q] + sm[7][q];
    }
}

// plain grid barrier: arrive + spin, last arriver releases
__device__ __forceinline__ void gbar(int slot, int tid) {
    __syncthreads();
    if (tid == 0) {
        __threadfence();
        atomicAdd(&g_bar[slot], 1);
        while (atomicAdd(&g_bar[slot], 0) < NB) __nanosleep(16);
        __threadfence();
    }
    __syncthreads();
}

// ---------------------------------------------------------------------------
// warp-cooperative exact 1-NN via expanding Chebyshev rings
__device__ __forceinline__ void nn_query(float sx, float sy, float sz,
                                         int lane, float& best_out, int& bj_out) {
    int cx = min(max((int)floorf((sx - GLO) * GINVH), 0), G - 1);
    int cy = min(max((int)floorf((sy - GLO) * GINVH), 0), G - 1);
    int cz = min(max((int)floorf((sz - GLO) * GINVH), 0), G - 1);
    int rmax = max(max(cx, G-1-cx), max(max(cy, G-1-cy), max(cz, G-1-cz)));

    float best = FLT_MAX;
    int   bj   = 0x7fffffff;
    int   r    = 1;
    bool  shell_only = false;
    for (;;) {
        int side = 2*r + 1;
        int ncells = side * side * side;
        for (int idx = lane; idx < ncells; idx += 32) {
            int dz = idx / (side * side);
            int rem = idx - dz * side * side;
            int dy = rem / side;
            int dx = rem - dy * side;
            dx -= r; dy -= r; dz -= r;
            if (shell_only && max(abs(dx), max(abs(dy), abs(dz))) < r) continue;
            int x = cx + dx, y = cy + dy, z = cz + dz;
            if (x < 0 || x >= G || y < 0 || y >= G || z < 0 || z >= G) continue;
            int c = (z * G + y) * G + x;
            int k0 = g_cellStart[c], k1 = g_cellStart[c + 1];
            for (int k = k0; k < k1; ++k) {
                float4 b = g_cellPts[k];
                float ddx = sx - b.x, ddy = sy - b.y, ddz = sz - b.z;
                float d2 = ddx*ddx + ddy*ddy + ddz*ddz;
                int j = __float_as_int(b.w);
                if (d2 < best || (d2 == best && j < bj)) { best = d2; bj = j; }
            }
        }
        // warp lexicographic min
        #pragma unroll
        for (int off = 16; off > 0; off >>= 1) {
            float od = __shfl_xor_sync(0xffffffffu, best, off);
            int   oj = __shfl_xor_sync(0xffffffffu, bj,   off);
            if (od < best || (od == best && oj < bj)) { best = od; bj = oj; }
        }
        // termination: margin = distance from query to scanned-box boundary
        float m = FLT_MAX;
        if (cx - r > 0)     m = fminf(m, sx - (GLO + (cx - r) * GH));
        if (cx + r < G - 1) m = fminf(m, (GLO + (cx + r + 1) * GH) - sx);
        if (cy - r > 0)     m = fminf(m, sy - (GLO + (cy - r) * GH));
        if (cy + r < G - 1) m = fminf(m, (GLO + (cy + r + 1) * GH) - sy);
        if (cz - r > 0)     m = fminf(m, sz - (GLO + (cz - r) * GH));
        if (cz + r < G - 1) m = fminf(m, (GLO + (cz + r + 1) * GH) - sz);
        if (best <= m * m) break;
        if (r >= rmax) break;
        ++r;
        shell_only = true;
    }
    best_out = best;
    bj_out = bj;
}

// ---------------------------------------------------------------------------
__global__ void __launch_bounds__(TPB, 2) k_icp(const float* __restrict__ A,
                                                const float* __restrict__ B,
                                                float* __restrict__ out) {
    __shared__ double sm[8][16];
    __shared__ int sscan[TPB];
    __shared__ int sbc;
    __shared__ int slast;
    const int tid  = threadIdx.x;
    const int bid  = blockIdx.x;
    const int gt   = bid * TPB + tid;
    const int lane = tid & 31;
    const int warp = tid >> 5;

    // ---- phase 0: zero counts, stage points ----
    g_cellCnt[gt] = 0;
    g_cellCnt[gt + 65536] = 0;
    if (gt < NPTS) {
        float ax = A[3*gt], ay = A[3*gt+1], az = A[3*gt+2];
        g_src4[gt] = make_float4(ax, ay, az, 0.f);
        float bx = B[3*gt], by = B[3*gt+1], bz = B[3*gt+2];
        g_B4[gt]   = make_float4(bx, by, bz, 0.f);
    }
    if (gt == 0) { g_done = 0; g_apply = 0; g_prev_err = 0.f; }
    gbar(0, tid);

    // ---- phase 1: count ----
    int mycell = -1;
    if (gt < NPTS) {
        float4 b = g_B4[gt];
        int cx = min(max((int)floorf((b.x - GLO) * GINVH), 0), G - 1);
        int cy = min(max((int)floorf((b.y - GLO) * GINVH), 0), G - 1);
        int cz = min(max((int)floorf((b.z - GLO) * GINVH), 0), G - 1);
        mycell = (cz * G + cy) * G + cx;
        atomicAdd(&g_cellCnt[mycell], 1);
    }
    gbar(1, tid);

    // ---- phase 2: per-thread 2 cells -> block scan -> block totals ----
    int t0 = gt * 2;
    int c0 = g_cellCnt[t0], c1 = g_cellCnt[t0 + 1];
    int s = c0 + c1;
    sscan[tid] = s;
    __syncthreads();
    for (int off = 1; off < TPB; off <<= 1) {
        int v = (tid >= off) ? sscan[tid - off] : 0;
        __syncthreads();
        sscan[tid] += v;
        __syncthreads();
    }
    int excl = sscan[tid] - s;
    if (tid == TPB - 1) g_bsum[bid] = sscan[TPB - 1];
    gbar(2, tid);

    // ---- phase 3: block offsets (redundant per-block reduce), cellStart ----
    {
        int v = (tid < bid) ? g_bsum[tid] : 0;
        sscan[tid] = v;
        __syncthreads();
        for (int off = TPB / 2; off > 0; off >>= 1) {
            if (tid < off) sscan[tid] += sscan[tid + off];
            __syncthreads();
        }
        if (tid == 0) sbc = sscan[0];
        __syncthreads();
        int base = sbc + excl;
        g_cellStart[t0]     = base;
        g_cellStart[t0 + 1] = base + c0;
        g_cellCnt[t0] = 0;              // cursors
        g_cellCnt[t0 + 1] = 0;
        if (gt == 65535) g_cellStart[CPAD] = base + c0 + c1;
    }
    gbar(3, tid);

    // ---- phase 4: scatter ----
    if (gt < NPTS) {
        float4 b = g_B4[gt];
        int pos = g_cellStart[mycell] + atomicAdd(&g_cellCnt[mycell], 1);
        g_cellPts[pos] = make_float4(b.x, b.y, b.z, __int_as_float(gt));
    }
    gbar(4, tid);

    // ---- iteration loop ----
    for (int it = 0; it < MAX_ITERS; ++it) {
        if (*(volatile int*)&g_done) break;

        double acc[16];
        #pragma unroll
        for (int q = 0; q < 16; ++q) acc[q] = 0.0;

        int apply = *(volatile int*)&g_apply;
        #pragma unroll 1
        for (int sidx = 0; sidx < 4; ++sidx) {
            int wsrc = (bid * 8 + warp) * 4 + sidx;
            float4 sp = g_src4[wsrc];
            float sx = sp.x, sy = sp.y, sz = sp.z;
            if (apply) {
                float x = g_T[0]*sx + g_T[1]*sy + g_T[2]*sz + g_T[9];
                float y = g_T[3]*sx + g_T[4]*sy + g_T[5]*sz + g_T[10];
                float z = g_T[6]*sx + g_T[7]*sy + g_T[8]*sz + g_T[11];
                sx = x; sy = y; sz = z;
                if (lane == 0) g_src4[wsrc] = make_float4(sx, sy, sz, 0.f);
            }
            float best; int bj;
            nn_query(sx, sy, sz, lane, best, bj);
            if (lane == 0) {
                float4 b = g_B4[bj];
                double dsx = sx, dsy = sy, dsz = sz;
                double dbx = b.x, dby = b.y, dbz = b.z;
                acc[0] += dsx;  acc[1] += dsy;  acc[2] += dsz;
                acc[3] += dbx;  acc[4] += dby;  acc[5] += dbz;
                acc[6]  += dsx*dbx; acc[7]  += dsx*dby; acc[8]  += dsx*dbz;
                acc[9]  += dsy*dbx; acc[10] += dsy*dby; acc[11] += dsy*dbz;
                acc[12] += dsz*dbx; acc[13] += dsz*dby; acc[14] += dsz*dbz;
                acc[15] += (double)sqrtf(fmaxf(best, 0.0f) + 1e-12f);
            }
        }
        block_reduce16(acc, sm, tid, bid);

        // iteration barrier with embedded solve
        int slot = 5 + it;
        if (tid == 0) slast = (atomicAdd(&g_bar[slot], 1) == NB - 1);
        __syncthreads();
        if (slast) {
            if (tid == 0) __threadfence();
            __syncthreads();
            double S[16];
            grid_sum16(S, sm, tid);
            if (tid == 0) {
                solve_iter(S);
                __threadfence();
                atomicAdd(&g_bar[slot], 1);    // release -> NB+1
            }
            __syncthreads();
        } else {
            if (tid == 0) {
                while (atomicAdd(&g_bar[slot], 0) <= NB) __nanosleep(16);
                __threadfence();
            }
            __syncthreads();
        }
    }

    // ---- final best-fit A -> src ----
    double v[16];
    if (bid < NPTS / TPB) {
        int i2 = bid * TPB + tid;
        float4 sp = g_src4[i2];
        float sx = sp.x, sy = sp.y, sz = sp.z;
        if (*(volatile int*)&g_apply) {
            float x = g_T[0]*sx + g_T[1]*sy + g_T[2]*sz + g_T[9];
            float y = g_T[3]*sx + g_T[4]*sy + g_T[5]*sz + g_T[10];
            float z = g_T[6]*sx + g_T[7]*sy + g_T[8]*sz + g_T[11];
            sx = x; sy = y; sz = z;
        }
        float ax = A[3*i2], ay = A[3*i2+1], az = A[3*i2+2];
        double pax = ax, pay = ay, paz = az;
        double pbx = sx, pby = sy, pbz = sz;
        v[0] = pax; v[1] = pay; v[2] = paz;
        v[3] = pbx; v[4] = pby; v[5] = pbz;
        v[6]  = pax*pbx; v[7]  = pax*pby; v[8]  = pax*pbz;
        v[9]  = pay*pbx; v[10] = pay*pby; v[11] = pay*pbz;
        v[12] = paz*pbx; v[13] = paz*pby; v[14] = paz*pbz;
        v[15] = 0.0;
    } else {
        #pragma unroll
        for (int q = 0; q < 16; ++q) v[q] = 0.0;
    }
    block_reduce16(v, sm, tid, bid);

    if (tid == 0) slast = (atomicAdd(&g_bar[NBAR - 1], 1) == NB - 1);
    __syncthreads();
    if (!slast) return;

    if (tid == 0) __threadfence();
    __syncthreads();
    double S[16];
    grid_sum16(S, sm, tid);
    if (tid == 0) {
        const double N = (double)NPTS;
        double cAd[3] = {S[0]/N, S[1]/N, S[2]/N};
        double cBd[3] = {S[3]/N, S[4]/N, S[5]/N};
        float H[9], cA[3], cB[3];
        #pragma unroll
        for (int r = 0; r < 3; ++r) {
            cA[r] = (float)cAd[r]; cB[r] = (float)cBd[r];
            #pragma unroll
            for (int c = 0; c < 3; ++c)
                H[r*3+c] = (float)(S[6 + 3*r + c]/N - cAd[r]*cBd[c]);
        }
        float R[9], t[3];
        kabsch3(H, cA, cB, R, t);
        #pragma unroll
        for (int r = 0; r < 3; ++r) {
            out[r*4+0] = R[r*3+0]; out[r*4+1] = R[r*3+1];
            out[r*4+2] = R[r*3+2]; out[r*4+3] = t[r];
        }
        out[12] = 0.f; out[13] = 0.f; out[14] = 0.f; out[15] = 1.f;
        #pragma unroll
        for (int sl = 0; sl < NBAR; ++sl) g_bar[sl] = 0;   // rearm for replay
    }
}

// ---------------------------------------------------------------------------
extern "C" void kernel_launch(void* const* d_in, const int* in_sizes, int n_in,
                              void* d_out, int out_size) {
    const float* A = (const float*)d_in[0];
    const float* B = (const float*)d_in[1];
    float* out = (float*)d_out;
    k_icp<<<NB, TPB>>>(A, B, out);
}